// round 1
// baseline (speedup 1.0000x reference)
#include <cuda_runtime.h>

#define DD 17
#define HH 8
#define OO 6
#define EE 4
#define G1 64
#define G2 32

// shared-memory float offsets
#define S_GW1 0            // 17*64 = 1088
#define S_GB1 1088         // 64
#define S_GW2 1152         // 64*32 = 2048
#define S_GB2 3200         // 32
#define S_GW3 3232         // 32*4 = 128
#define S_GB3 3360         // 4
#define S_EW1 3364         // 4*17*8 = 544
#define S_EB1 3908         // 32
#define S_EW2 3940         // 4*8*8 = 256
#define S_EB2 4196         // 32
#define S_EW3 4228         // 4*8*6 = 192
#define S_EB3 4420         // 24
#define S_TOT 4444

__global__ __launch_bounds__(256) void moe_kernel(
    const float* __restrict__ x,
    const float* __restrict__ eW1, const float* __restrict__ eb1,
    const float* __restrict__ eW2, const float* __restrict__ eb2,
    const float* __restrict__ eW3, const float* __restrict__ eb3,
    const float* __restrict__ gW1, const float* __restrict__ gb1,
    const float* __restrict__ gW2, const float* __restrict__ gb2,
    const float* __restrict__ gW3, const float* __restrict__ gb3,
    float* __restrict__ pred, float* __restrict__ glog, int B)
{
    __shared__ float s[S_TOT];
    const int t = threadIdx.x;
    // cooperative weight staging (block-wide)
    for (int i = t; i < 1088; i += 256) s[S_GW1 + i] = gW1[i];
    for (int i = t; i < 64;   i += 256) s[S_GB1 + i] = gb1[i];
    for (int i = t; i < 2048; i += 256) s[S_GW2 + i] = gW2[i];
    for (int i = t; i < 32;   i += 256) s[S_GB2 + i] = gb2[i];
    for (int i = t; i < 128;  i += 256) s[S_GW3 + i] = gW3[i];
    for (int i = t; i < 4;    i += 256) s[S_GB3 + i] = gb3[i];
    for (int i = t; i < 544;  i += 256) s[S_EW1 + i] = eW1[i];
    for (int i = t; i < 32;   i += 256) s[S_EB1 + i] = eb1[i];
    for (int i = t; i < 256;  i += 256) s[S_EW2 + i] = eW2[i];
    for (int i = t; i < 32;   i += 256) s[S_EB2 + i] = eb2[i];
    for (int i = t; i < 192;  i += 256) s[S_EW3 + i] = eW3[i];
    for (int i = t; i < 24;   i += 256) s[S_EB3 + i] = eb3[i];
    __syncthreads();

    const int b = blockIdx.x * 256 + t;
    if (b >= B) return;

    // load input row (17 floats)
    float xv[DD];
    const float* xr = x + (size_t)b * DD;
#pragma unroll
    for (int i = 0; i < DD; i++) xv[i] = xr[i];

    // ---- gating layer 2 accumulators (init with bias) ----
    float h2[G2];
#pragma unroll
    for (int k = 0; k < G2; k++) h2[k] = s[S_GB2 + k];

    // ---- gating layer 1 in chunks of 16 to cap registers, fused into layer 2 ----
#pragma unroll
    for (int c = 0; c < 4; c++) {
        float h1[16];
#pragma unroll
        for (int j = 0; j < 16; j++) h1[j] = s[S_GB1 + c * 16 + j];
#pragma unroll
        for (int i = 0; i < DD; i++) {
            const float xi = xv[i];
#pragma unroll
            for (int j = 0; j < 16; j++)
                h1[j] = fmaf(xi, s[S_GW1 + i * G1 + c * 16 + j], h1[j]);
        }
#pragma unroll
        for (int j = 0; j < 16; j++) h1[j] = fmaxf(h1[j], 0.0f);
#pragma unroll
        for (int j = 0; j < 16; j++) {
            const float hj = h1[j];
            const int row = (c * 16 + j) * G2;
#pragma unroll
            for (int k = 0; k < G2; k++)
                h2[k] = fmaf(hj, s[S_GW2 + row + k], h2[k]);
        }
    }
#pragma unroll
    for (int k = 0; k < G2; k++) h2[k] = fmaxf(h2[k], 0.0f);

    // ---- gating layer 3: logits ----
    float lg[EE];
#pragma unroll
    for (int e = 0; e < EE; e++) lg[e] = s[S_GB3 + e];
#pragma unroll
    for (int k = 0; k < G2; k++) {
        const float hk = h2[k];
#pragma unroll
        for (int e = 0; e < EE; e++)
            lg[e] = fmaf(hk, s[S_GW3 + k * EE + e], lg[e]);
    }

    // argmax, first-max-wins (matches jnp.argmax)
    int sel = 0;
    float m = lg[0];
#pragma unroll
    for (int e = 1; e < EE; e++) {
        if (lg[e] > m) { m = lg[e]; sel = e; }
    }

    // ---- selected expert only (output of unselected experts is unobservable) ----
    float e1[HH];
#pragma unroll
    for (int h = 0; h < HH; h++) e1[h] = s[S_EB1 + sel * HH + h];
#pragma unroll
    for (int i = 0; i < DD; i++) {
        const float xi = xv[i];
        const int row = S_EW1 + (sel * DD + i) * HH;
#pragma unroll
        for (int h = 0; h < HH; h++)
            e1[h] = fmaf(xi, s[row + h], e1[h]);
    }
#pragma unroll
    for (int h = 0; h < HH; h++) e1[h] = fmaxf(e1[h], 0.0f);

    float e2[HH];
#pragma unroll
    for (int k = 0; k < HH; k++) e2[k] = s[S_EB2 + sel * HH + k];
#pragma unroll
    for (int h = 0; h < HH; h++) {
        const float eh = e1[h];
        const int row = S_EW2 + (sel * HH + h) * HH;
#pragma unroll
        for (int k = 0; k < HH; k++)
            e2[k] = fmaf(eh, s[row + k], e2[k]);
    }
#pragma unroll
    for (int k = 0; k < HH; k++) e2[k] = fmaxf(e2[k], 0.0f);

    float eo[OO];
#pragma unroll
    for (int o = 0; o < OO; o++) eo[o] = s[S_EB3 + sel * OO + o];
#pragma unroll
    for (int k = 0; k < HH; k++) {
        const float ek = e2[k];
        const int row = S_EW3 + (sel * HH + k) * OO;
#pragma unroll
        for (int o = 0; o < OO; o++)
            eo[o] = fmaf(ek, s[row + o], eo[o]);
    }

    // ---- outputs ----
    // predictions [B, 6] then gating_logits [B, 4] (reference return order, flattened)
    float2* pout = (float2*)(pred + (size_t)b * OO);
    pout[0] = make_float2(eo[0], eo[1]);
    pout[1] = make_float2(eo[2], eo[3]);
    pout[2] = make_float2(eo[4], eo[5]);
    float4* lout = (float4*)(glog + (size_t)b * EE);
    lout[0] = make_float4(lg[0], lg[1], lg[2], lg[3]);
}

extern "C" void kernel_launch(void* const* d_in, const int* in_sizes, int n_in,
                              void* d_out, int out_size) {
    const float* x   = (const float*)d_in[0];
    const float* eW1 = (const float*)d_in[1];
    const float* eb1 = (const float*)d_in[2];
    const float* eW2 = (const float*)d_in[3];
    const float* eb2 = (const float*)d_in[4];
    const float* eW3 = (const float*)d_in[5];
    const float* eb3 = (const float*)d_in[6];
    const float* gW1 = (const float*)d_in[7];
    const float* gb1 = (const float*)d_in[8];
    const float* gW2 = (const float*)d_in[9];
    const float* gb2 = (const float*)d_in[10];
    const float* gW3 = (const float*)d_in[11];
    const float* gb3 = (const float*)d_in[12];

    const int B = in_sizes[0] / DD;
    float* out  = (float*)d_out;
    float* pred = out;                      // [B, 6]
    float* glog = out + (size_t)B * OO;     // [B, 4]

    const int grid = (B + 255) / 256;
    moe_kernel<<<grid, 256>>>(x, eW1, eb1, eW2, eb2, eW3, eb3,
                              gW1, gb1, gW2, gb2, gW3, gb3,
                              pred, glog, B);
}

// round 2
// speedup vs baseline: 1.1486x; 1.1486x over previous
#include <cuda_runtime.h>
#include <cstdint>

typedef unsigned long long u64;

#define DD 17
#define HH 8
#define OO 6
#define EE 4

// shared-memory float offsets (all packed-load bases 16B or 8B aligned)
#define S_GW1 0            // 17*64 = 1088
#define S_GB1 1088         // 64
#define S_GW2 1152         // 64*32 = 2048
#define S_GB2 3200         // 32
#define S_GW3 3232         // 32*4 = 128
#define S_GB3 3360         // 4
#define S_GB3P 3360        // padded region: use 3360..3363 (4 floats, 16B aligned)
#define S_EW1 3364         // 4*17*8 = 544
#define S_EB1 3908         // 4*8 = 32
#define S_EW2 3940         // 4*8*8 = 256
#define S_EB2 4196         // 32
#define S_EW3 4228         // 4*8*6 = 192
#define S_EB3 4420         // 24
#define S_TOT 4448

__device__ __forceinline__ u64 pk2(float lo, float hi) {
    u64 r; asm("mov.b64 %0, {%1,%2};" : "=l"(r) : "f"(lo), "f"(hi)); return r;
}
__device__ __forceinline__ u64 dup2(float v) { return pk2(v, v); }
__device__ __forceinline__ void upk2(u64 v, float& lo, float& hi) {
    asm("mov.b64 {%0,%1}, %2;" : "=f"(lo), "=f"(hi) : "l"(v));
}
__device__ __forceinline__ u64 ffma2(u64 a, u64 b, u64 c) {
    u64 d; asm("fma.rn.f32x2 %0, %1, %2, %3;" : "=l"(d) : "l"(a), "l"(b), "l"(c)); return d;
}

__global__ __launch_bounds__(256, 2) void moe_kernel(
    const float* __restrict__ x,
    const float* __restrict__ eW1, const float* __restrict__ eb1,
    const float* __restrict__ eW2, const float* __restrict__ eb2,
    const float* __restrict__ eW3, const float* __restrict__ eb3,
    const float* __restrict__ gW1, const float* __restrict__ gb1,
    const float* __restrict__ gW2, const float* __restrict__ gb2,
    const float* __restrict__ gW3, const float* __restrict__ gb3,
    float* __restrict__ pred, float* __restrict__ glog, int B)
{
    __shared__ __align__(16) float s[S_TOT];
    const int t = threadIdx.x;
    for (int i = t; i < 1088; i += 256) s[S_GW1 + i] = gW1[i];
    for (int i = t; i < 64;   i += 256) s[S_GB1 + i] = gb1[i];
    for (int i = t; i < 2048; i += 256) s[S_GW2 + i] = gW2[i];
    for (int i = t; i < 32;   i += 256) s[S_GB2 + i] = gb2[i];
    for (int i = t; i < 128;  i += 256) s[S_GW3 + i] = gW3[i];
    for (int i = t; i < 4;    i += 256) s[S_GB3 + i] = gb3[i];
    for (int i = t; i < 544;  i += 256) s[S_EW1 + i] = eW1[i];
    for (int i = t; i < 32;   i += 256) s[S_EB1 + i] = eb1[i];
    for (int i = t; i < 256;  i += 256) s[S_EW2 + i] = eW2[i];
    for (int i = t; i < 32;   i += 256) s[S_EB2 + i] = eb2[i];
    for (int i = t; i < 192;  i += 256) s[S_EW3 + i] = eW3[i];
    for (int i = t; i < 24;   i += 256) s[S_EB3 + i] = eb3[i];
    __syncthreads();

    const int b = blockIdx.x * 256 + t;
    if (b >= B) return;

    float xv[DD];
    const float* xr = x + (size_t)b * DD;
#pragma unroll
    for (int i = 0; i < DD; i++) xv[i] = xr[i];

    // ---- gating layer 2 accumulators, packed pairs (init with bias) ----
    u64 h2p[16];
    {
        const ulonglong2* bp = (const ulonglong2*)&s[S_GB2];
#pragma unroll
        for (int q = 0; q < 8; q++) { ulonglong2 v = bp[q]; h2p[2*q] = v.x; h2p[2*q+1] = v.y; }
    }

    // ---- layer1 in 16-neuron chunks, fused into layer2 ----
#pragma unroll
    for (int c = 0; c < 4; c++) {
        u64 h1p[8];
        {
            const ulonglong2* bp = (const ulonglong2*)&s[S_GB1 + c * 16];
#pragma unroll
            for (int q = 0; q < 4; q++) { ulonglong2 v = bp[q]; h1p[2*q] = v.x; h1p[2*q+1] = v.y; }
        }
#pragma unroll
        for (int i = 0; i < DD; i++) {
            const u64 xi2 = dup2(xv[i]);
            const ulonglong2* wp = (const ulonglong2*)&s[S_GW1 + i * 64 + c * 16];
#pragma unroll
            for (int q = 0; q < 4; q++) {
                ulonglong2 w = wp[q];
                h1p[2*q]   = ffma2(xi2, w.x, h1p[2*q]);
                h1p[2*q+1] = ffma2(xi2, w.y, h1p[2*q+1]);
            }
        }
        // relu + feed into layer 2 (32-wide rows, packed)
#pragma unroll
        for (int p = 0; p < 8; p++) {
            float a, bb; upk2(h1p[p], a, bb);
#pragma unroll
            for (int half = 0; half < 2; half++) {
                const float hv = fmaxf(half ? bb : a, 0.0f);
                const u64 hd = dup2(hv);
                const int j = c * 16 + 2 * p + half;
                const ulonglong2* wp = (const ulonglong2*)&s[S_GW2 + j * 32];
#pragma unroll
                for (int q = 0; q < 8; q++) {
                    ulonglong2 w = wp[q];
                    h2p[2*q]   = ffma2(hd, w.x, h2p[2*q]);
                    h2p[2*q+1] = ffma2(hd, w.y, h2p[2*q+1]);
                }
            }
        }
    }

    // ---- layer 3: relu(h2) -> 4 logits, packed ----
    u64 lgp0, lgp1;
    {
        ulonglong2 bv = *(const ulonglong2*)&s[S_GB3];
        lgp0 = bv.x; lgp1 = bv.y;
    }
#pragma unroll
    for (int p = 0; p < 16; p++) {
        float a, bb; upk2(h2p[p], a, bb);
#pragma unroll
        for (int half = 0; half < 2; half++) {
            const float hv = fmaxf(half ? bb : a, 0.0f);
            const u64 hd = dup2(hv);
            const int k = 2 * p + half;
            ulonglong2 w = *(const ulonglong2*)&s[S_GW3 + k * 4];
            lgp0 = ffma2(hd, w.x, lgp0);
            lgp1 = ffma2(hd, w.y, lgp1);
        }
    }
    float l0, l1, l2, l3;
    upk2(lgp0, l0, l1);
    upk2(lgp1, l2, l3);

    // argmax, first-max-wins (matches jnp.argmax)
    int sel = 0; float m = l0;
    if (l1 > m) { m = l1; sel = 1; }
    if (l2 > m) { m = l2; sel = 2; }
    if (l3 > m) { m = l3; sel = 3; }

    // ---- selected expert only ----
    u64 e1p[4];
    {
        const ulonglong2* bp = (const ulonglong2*)&s[S_EB1 + sel * HH];
        ulonglong2 v0 = bp[0], v1 = bp[1];
        e1p[0] = v0.x; e1p[1] = v0.y; e1p[2] = v1.x; e1p[3] = v1.y;
    }
#pragma unroll
    for (int i = 0; i < DD; i++) {
        const u64 xi2 = dup2(xv[i]);
        const ulonglong2* wp = (const ulonglong2*)&s[S_EW1 + (sel * DD + i) * HH];
        ulonglong2 w0 = wp[0], w1 = wp[1];
        e1p[0] = ffma2(xi2, w0.x, e1p[0]);
        e1p[1] = ffma2(xi2, w0.y, e1p[1]);
        e1p[2] = ffma2(xi2, w1.x, e1p[2]);
        e1p[3] = ffma2(xi2, w1.y, e1p[3]);
    }
    float e1[HH];
    upk2(e1p[0], e1[0], e1[1]); upk2(e1p[1], e1[2], e1[3]);
    upk2(e1p[2], e1[4], e1[5]); upk2(e1p[3], e1[6], e1[7]);
#pragma unroll
    for (int h = 0; h < HH; h++) e1[h] = fmaxf(e1[h], 0.0f);

    u64 e2p[4];
    {
        const ulonglong2* bp = (const ulonglong2*)&s[S_EB2 + sel * HH];
        ulonglong2 v0 = bp[0], v1 = bp[1];
        e2p[0] = v0.x; e2p[1] = v0.y; e2p[2] = v1.x; e2p[3] = v1.y;
    }
#pragma unroll
    for (int h = 0; h < HH; h++) {
        const u64 hd = dup2(e1[h]);
        const ulonglong2* wp = (const ulonglong2*)&s[S_EW2 + (sel * HH + h) * HH];
        ulonglong2 w0 = wp[0], w1 = wp[1];
        e2p[0] = ffma2(hd, w0.x, e2p[0]);
        e2p[1] = ffma2(hd, w0.y, e2p[1]);
        e2p[2] = ffma2(hd, w1.x, e2p[2]);
        e2p[3] = ffma2(hd, w1.y, e2p[3]);
    }
    float e2[HH];
    upk2(e2p[0], e2[0], e2[1]); upk2(e2p[1], e2[2], e2[3]);
    upk2(e2p[2], e2[4], e2[5]); upk2(e2p[3], e2[6], e2[7]);
#pragma unroll
    for (int k = 0; k < HH; k++) e2[k] = fmaxf(e2[k], 0.0f);

    u64 eop0, eop1, eop2;
    {
        const u64* bp = (const u64*)&s[S_EB3 + sel * OO];
        eop0 = bp[0]; eop1 = bp[1]; eop2 = bp[2];
    }
#pragma unroll
    for (int k = 0; k < HH; k++) {
        const u64 kd = dup2(e2[k]);
        const u64* wp = (const u64*)&s[S_EW3 + (sel * HH + k) * OO];
        eop0 = ffma2(kd, wp[0], eop0);
        eop1 = ffma2(kd, wp[1], eop1);
        eop2 = ffma2(kd, wp[2], eop2);
    }

    // ---- outputs: packed pairs store directly as (lo,hi) float pairs ----
    u64* pout = (u64*)(pred + (size_t)b * OO);
    pout[0] = eop0; pout[1] = eop1; pout[2] = eop2;
    ulonglong2* lout = (ulonglong2*)(glog + (size_t)b * EE);
    lout[0] = make_ulonglong2(lgp0, lgp1);
}

extern "C" void kernel_launch(void* const* d_in, const int* in_sizes, int n_in,
                              void* d_out, int out_size) {
    const float* x   = (const float*)d_in[0];
    const float* eW1 = (const float*)d_in[1];
    const float* eb1 = (const float*)d_in[2];
    const float* eW2 = (const float*)d_in[3];
    const float* eb2 = (const float*)d_in[4];
    const float* eW3 = (const float*)d_in[5];
    const float* eb3 = (const float*)d_in[6];
    const float* gW1 = (const float*)d_in[7];
    const float* gb1 = (const float*)d_in[8];
    const float* gW2 = (const float*)d_in[9];
    const float* gb2 = (const float*)d_in[10];
    const float* gW3 = (const float*)d_in[11];
    const float* gb3 = (const float*)d_in[12];

    const int B = in_sizes[0] / DD;
    float* out  = (float*)d_out;
    float* pred = out;                   // [B, 6]
    float* glog = out + (size_t)B * OO;  // [B, 4]

    const int grid = (B + 255) / 256;
    moe_kernel<<<grid, 256>>>(x, eW1, eb1, eW2, eb2, eW3, eb3,
                              gW1, gb1, gW2, gb2, gW3, gb3,
                              pred, glog, B);
}

// round 3
// speedup vs baseline: 1.4833x; 1.2914x over previous
#include <cuda_runtime.h>

typedef unsigned long long u64;

#define DD 17
#define HH 8
#define OO 6
#define EE 4

// shared-memory float offsets
#define S_GW1 0            // 1088
#define S_GB1 1088         // 64
#define S_GW2 1152         // 2048
#define S_GB2 3200         // 32
#define S_GW3 3232         // 128
#define S_GB3 3360         // 4
#define S_EW1 3364         // 544
#define S_EB1 3908         // 32
#define S_EW2 3940         // 256
#define S_EB2 4196         // 32
#define S_EW3 4228         // 192
#define S_EB3 4420         // 24
#define S_TOT 4448

__device__ __forceinline__ u64 pk2(float lo, float hi) {
    u64 r; asm("mov.b64 %0, {%1,%2};" : "=l"(r) : "f"(lo), "f"(hi)); return r;
}
__device__ __forceinline__ u64 dup2(float v) { return pk2(v, v); }
__device__ __forceinline__ void upk2(u64 v, float& lo, float& hi) {
    asm("mov.b64 {%0,%1}, %2;" : "=f"(lo), "=f"(hi) : "l"(v));
}
__device__ __forceinline__ u64 ffma2(u64 a, u64 b, u64 c) {
    u64 d; asm("fma.rn.f32x2 %0, %1, %2, %3;" : "=l"(d) : "l"(a), "l"(b), "l"(c)); return d;
}

// selected-expert MLP, exact fp32 (packed) arithmetic
__device__ __forceinline__ void expert_eval(const float* __restrict__ s,
                                            const float xv[DD], int sel,
                                            u64& o0, u64& o1, u64& o2)
{
    u64 e1p[4];
    {
        const ulonglong2* bp = (const ulonglong2*)&s[S_EB1 + sel * HH];
        ulonglong2 v0 = bp[0], v1 = bp[1];
        e1p[0] = v0.x; e1p[1] = v0.y; e1p[2] = v1.x; e1p[3] = v1.y;
    }
#pragma unroll
    for (int i = 0; i < DD; i++) {
        const u64 xi2 = dup2(xv[i]);
        const ulonglong2* wp = (const ulonglong2*)&s[S_EW1 + (sel * DD + i) * HH];
        ulonglong2 w0 = wp[0], w1 = wp[1];
        e1p[0] = ffma2(xi2, w0.x, e1p[0]);
        e1p[1] = ffma2(xi2, w0.y, e1p[1]);
        e1p[2] = ffma2(xi2, w1.x, e1p[2]);
        e1p[3] = ffma2(xi2, w1.y, e1p[3]);
    }
    float e1[HH];
    upk2(e1p[0], e1[0], e1[1]); upk2(e1p[1], e1[2], e1[3]);
    upk2(e1p[2], e1[4], e1[5]); upk2(e1p[3], e1[6], e1[7]);
#pragma unroll
    for (int h = 0; h < HH; h++) e1[h] = fmaxf(e1[h], 0.0f);

    u64 e2p[4];
    {
        const ulonglong2* bp = (const ulonglong2*)&s[S_EB2 + sel * HH];
        ulonglong2 v0 = bp[0], v1 = bp[1];
        e2p[0] = v0.x; e2p[1] = v0.y; e2p[2] = v1.x; e2p[3] = v1.y;
    }
#pragma unroll
    for (int h = 0; h < HH; h++) {
        const u64 hd = dup2(e1[h]);
        const ulonglong2* wp = (const ulonglong2*)&s[S_EW2 + (sel * HH + h) * HH];
        ulonglong2 w0 = wp[0], w1 = wp[1];
        e2p[0] = ffma2(hd, w0.x, e2p[0]);
        e2p[1] = ffma2(hd, w0.y, e2p[1]);
        e2p[2] = ffma2(hd, w1.x, e2p[2]);
        e2p[3] = ffma2(hd, w1.y, e2p[3]);
    }
    float e2[HH];
    upk2(e2p[0], e2[0], e2[1]); upk2(e2p[1], e2[2], e2[3]);
    upk2(e2p[2], e2[4], e2[5]); upk2(e2p[3], e2[6], e2[7]);
#pragma unroll
    for (int k = 0; k < HH; k++) e2[k] = fmaxf(e2[k], 0.0f);

    {
        const u64* bp = (const u64*)&s[S_EB3 + sel * OO];
        o0 = bp[0]; o1 = bp[1]; o2 = bp[2];
    }
#pragma unroll
    for (int k = 0; k < HH; k++) {
        const u64 kd = dup2(e2[k]);
        const u64* wp = (const u64*)&s[S_EW3 + (sel * HH + k) * OO];
        o0 = ffma2(kd, wp[0], o0);
        o1 = ffma2(kd, wp[1], o1);
        o2 = ffma2(kd, wp[2], o2);
    }
}

__global__ __launch_bounds__(128) void moe_kernel(
    const float* __restrict__ x,
    const float* __restrict__ eW1, const float* __restrict__ eb1,
    const float* __restrict__ eW2, const float* __restrict__ eb2,
    const float* __restrict__ eW3, const float* __restrict__ eb3,
    const float* __restrict__ gW1, const float* __restrict__ gb1,
    const float* __restrict__ gW2, const float* __restrict__ gb2,
    const float* __restrict__ gW3, const float* __restrict__ gb3,
    float* __restrict__ pred, float* __restrict__ glog, int Bhalf)
{
    __shared__ __align__(16) float s[S_TOT];
    const int t = threadIdx.x;
    for (int i = t; i < 1088; i += 128) s[S_GW1 + i] = gW1[i];
    for (int i = t; i < 64;   i += 128) s[S_GB1 + i] = gb1[i];
    for (int i = t; i < 2048; i += 128) s[S_GW2 + i] = gW2[i];
    for (int i = t; i < 32;   i += 128) s[S_GB2 + i] = gb2[i];
    for (int i = t; i < 128;  i += 128) s[S_GW3 + i] = gW3[i];
    for (int i = t; i < 4;    i += 128) s[S_GB3 + i] = gb3[i];
    for (int i = t; i < 544;  i += 128) s[S_EW1 + i] = eW1[i];
    for (int i = t; i < 32;   i += 128) s[S_EB1 + i] = eb1[i];
    for (int i = t; i < 256;  i += 128) s[S_EW2 + i] = eW2[i];
    for (int i = t; i < 32;   i += 128) s[S_EB2 + i] = eb2[i];
    for (int i = t; i < 192;  i += 128) s[S_EW3 + i] = eW3[i];
    for (int i = t; i < 24;   i += 128) s[S_EB3 + i] = eb3[i];
    __syncthreads();

    const int ba = blockIdx.x * 128 + t;   // first sample
    const int bb = ba + Bhalf;             // second sample (coalesced pairing)

    // load both input rows
    float xa[DD], xb[DD];
    {
        const float* ra = x + (size_t)ba * DD;
        const float* rb = x + (size_t)bb * DD;
#pragma unroll
        for (int i = 0; i < DD; i++) { xa[i] = ra[i]; xb[i] = rb[i]; }
    }

    // gating layer-2 accumulators for both samples (init with bias)
    u64 A2[16], B2[16];
    {
        const ulonglong2* bp = (const ulonglong2*)&s[S_GB2];
#pragma unroll
        for (int q = 0; q < 8; q++) {
            ulonglong2 v = bp[q];
            A2[2*q] = v.x; A2[2*q+1] = v.y;
            B2[2*q] = v.x; B2[2*q+1] = v.y;
        }
    }

    // layer1 in 16-neuron chunks, fused into layer2 — each weight load feeds 2 samples
#pragma unroll
    for (int c = 0; c < 4; c++) {
        u64 A1[8], B1[8];
        {
            const ulonglong2* bp = (const ulonglong2*)&s[S_GB1 + c * 16];
#pragma unroll
            for (int q = 0; q < 4; q++) {
                ulonglong2 v = bp[q];
                A1[2*q] = v.x; A1[2*q+1] = v.y;
                B1[2*q] = v.x; B1[2*q+1] = v.y;
            }
        }
#pragma unroll
        for (int i = 0; i < DD; i++) {
            const u64 xad = dup2(xa[i]);
            const u64 xbd = dup2(xb[i]);
            const ulonglong2* wp = (const ulonglong2*)&s[S_GW1 + i * 64 + c * 16];
#pragma unroll
            for (int q = 0; q < 4; q++) {
                ulonglong2 w = wp[q];
                A1[2*q]   = ffma2(xad, w.x, A1[2*q]);
                B1[2*q]   = ffma2(xbd, w.x, B1[2*q]);
                A1[2*q+1] = ffma2(xad, w.y, A1[2*q+1]);
                B1[2*q+1] = ffma2(xbd, w.y, B1[2*q+1]);
            }
        }
        // relu + feed into layer 2
#pragma unroll
        for (int p = 0; p < 8; p++) {
            float a0, a1, b0, b1;
            upk2(A1[p], a0, a1);
            upk2(B1[p], b0, b1);
#pragma unroll
            for (int half = 0; half < 2; half++) {
                const u64 had = dup2(fmaxf(half ? a1 : a0, 0.0f));
                const u64 hbd = dup2(fmaxf(half ? b1 : b0, 0.0f));
                const int j = c * 16 + 2 * p + half;
                const ulonglong2* wp = (const ulonglong2*)&s[S_GW2 + j * 32];
#pragma unroll
                for (int q = 0; q < 8; q++) {
                    ulonglong2 w = wp[q];
                    A2[2*q]   = ffma2(had, w.x, A2[2*q]);
                    B2[2*q]   = ffma2(hbd, w.x, B2[2*q]);
                    A2[2*q+1] = ffma2(had, w.y, A2[2*q+1]);
                    B2[2*q+1] = ffma2(hbd, w.y, B2[2*q+1]);
                }
            }
        }
    }

    // layer 3: relu(h2) -> 4 logits (both samples)
    u64 lgA0, lgA1, lgB0, lgB1;
    {
        ulonglong2 bv = *(const ulonglong2*)&s[S_GB3];
        lgA0 = bv.x; lgA1 = bv.y;
        lgB0 = bv.x; lgB1 = bv.y;
    }
#pragma unroll
    for (int p = 0; p < 16; p++) {
        float a0, a1, b0, b1;
        upk2(A2[p], a0, a1);
        upk2(B2[p], b0, b1);
#pragma unroll
        for (int half = 0; half < 2; half++) {
            const u64 had = dup2(fmaxf(half ? a1 : a0, 0.0f));
            const u64 hbd = dup2(fmaxf(half ? b1 : b0, 0.0f));
            const int k = 2 * p + half;
            ulonglong2 w = *(const ulonglong2*)&s[S_GW3 + k * 4];
            lgA0 = ffma2(had, w.x, lgA0);
            lgB0 = ffma2(hbd, w.x, lgB0);
            lgA1 = ffma2(had, w.y, lgA1);
            lgB1 = ffma2(hbd, w.y, lgB1);
        }
    }

    // argmax (first-max-wins) per sample
    float la0, la1, la2, la3, lb0, lb1, lb2, lb3;
    upk2(lgA0, la0, la1); upk2(lgA1, la2, la3);
    upk2(lgB0, lb0, lb1); upk2(lgB1, lb2, lb3);
    int selA = 0; float mA = la0;
    if (la1 > mA) { mA = la1; selA = 1; }
    if (la2 > mA) { mA = la2; selA = 2; }
    if (la3 > mA) { mA = la3; selA = 3; }
    int selB = 0; float mB = lb0;
    if (lb1 > mB) { mB = lb1; selB = 1; }
    if (lb2 > mB) { mB = lb2; selB = 2; }
    if (lb3 > mB) { mB = lb3; selB = 3; }

    // selected experts
    u64 oA0, oA1, oA2, oB0, oB1, oB2;
    expert_eval(s, xa, selA, oA0, oA1, oA2);
    expert_eval(s, xb, selB, oB0, oB1, oB2);

    // stores
    {
        u64* p0 = (u64*)(pred + (size_t)ba * OO);
        p0[0] = oA0; p0[1] = oA1; p0[2] = oA2;
        u64* p1 = (u64*)(pred + (size_t)bb * OO);
        p1[0] = oB0; p1[1] = oB1; p1[2] = oB2;
        ulonglong2* l0 = (ulonglong2*)(glog + (size_t)ba * EE);
        l0[0] = make_ulonglong2(lgA0, lgA1);
        ulonglong2* l1 = (ulonglong2*)(glog + (size_t)bb * EE);
        l1[0] = make_ulonglong2(lgB0, lgB1);
    }
}

extern "C" void kernel_launch(void* const* d_in, const int* in_sizes, int n_in,
                              void* d_out, int out_size) {
    const float* x   = (const float*)d_in[0];
    const float* eW1 = (const float*)d_in[1];
    const float* eb1 = (const float*)d_in[2];
    const float* eW2 = (const float*)d_in[3];
    const float* eb2 = (const float*)d_in[4];
    const float* eW3 = (const float*)d_in[5];
    const float* eb3 = (const float*)d_in[6];
    const float* gW1 = (const float*)d_in[7];
    const float* gb1 = (const float*)d_in[8];
    const float* gW2 = (const float*)d_in[9];
    const float* gb2 = (const float*)d_in[10];
    const float* gW3 = (const float*)d_in[11];
    const float* gb3 = (const float*)d_in[12];

    const int B = in_sizes[0] / DD;
    float* out  = (float*)d_out;
    float* pred = out;                   // [B, 6]
    float* glog = out + (size_t)B * OO;  // [B, 4]

    const int grid = B / 256;            // 128 threads/block, 2 samples/thread
    moe_kernel<<<grid, 128>>>(x, eW1, eb1, eW2, eb2, eW3, eb3,
                              gW1, gb1, gW2, gb2, gW3, gb3,
                              pred, glog, B / 2);
}

// round 4
// speedup vs baseline: 1.6196x; 1.0919x over previous
#include <cuda_runtime.h>

typedef unsigned long long u64;

#define DD 17
#define HH 8
#define OO 6
#define EE 4

// __constant__ gating weights (warp-uniform access -> LDCU/uniform path)
#define C_GW1 0            // 1088
#define C_GB1 1088         // 64
#define C_GW2 1152         // 2048
#define C_GB2 3200         // 32
#define C_GW3 3232         // 128
#define C_GB3 3360         // 4
#define C_TOT 3364
__constant__ __align__(16) float cw[C_TOT + 4];

// shared-memory expert weights (per-thread sel-indexed -> divergent, keep in smem)
#define S_EW1 0            // 544
#define S_EB1 544          // 32
#define S_EW2 576          // 256
#define S_EB2 832          // 32
#define S_EW3 864          // 192
#define S_EB3 1056         // 24
#define S_TOT 1080

__device__ __forceinline__ u64 pk2(float lo, float hi) {
    u64 r; asm("mov.b64 %0, {%1,%2};" : "=l"(r) : "f"(lo), "f"(hi)); return r;
}
__device__ __forceinline__ u64 dup2(float v) { return pk2(v, v); }
__device__ __forceinline__ void upk2(u64 v, float& lo, float& hi) {
    asm("mov.b64 {%0,%1}, %2;" : "=f"(lo), "=f"(hi) : "l"(v));
}
__device__ __forceinline__ u64 ffma2(u64 a, u64 b, u64 c) {
    u64 d; asm("fma.rn.f32x2 %0, %1, %2, %3;" : "=l"(d) : "l"(a), "l"(b), "l"(c)); return d;
}

// selected-expert MLP, exact fp32 (packed) arithmetic, weights from smem
__device__ __forceinline__ void expert_eval(const float* __restrict__ s,
                                            const float xv[DD], int sel,
                                            u64& o0, u64& o1, u64& o2)
{
    u64 e1p[4];
    {
        const ulonglong2* bp = (const ulonglong2*)&s[S_EB1 + sel * HH];
        ulonglong2 v0 = bp[0], v1 = bp[1];
        e1p[0] = v0.x; e1p[1] = v0.y; e1p[2] = v1.x; e1p[3] = v1.y;
    }
#pragma unroll
    for (int i = 0; i < DD; i++) {
        const u64 xi2 = dup2(xv[i]);
        const ulonglong2* wp = (const ulonglong2*)&s[S_EW1 + (sel * DD + i) * HH];
        ulonglong2 w0 = wp[0], w1 = wp[1];
        e1p[0] = ffma2(xi2, w0.x, e1p[0]);
        e1p[1] = ffma2(xi2, w0.y, e1p[1]);
        e1p[2] = ffma2(xi2, w1.x, e1p[2]);
        e1p[3] = ffma2(xi2, w1.y, e1p[3]);
    }
    float e1[HH];
    upk2(e1p[0], e1[0], e1[1]); upk2(e1p[1], e1[2], e1[3]);
    upk2(e1p[2], e1[4], e1[5]); upk2(e1p[3], e1[6], e1[7]);
#pragma unroll
    for (int h = 0; h < HH; h++) e1[h] = fmaxf(e1[h], 0.0f);

    u64 e2p[4];
    {
        const ulonglong2* bp = (const ulonglong2*)&s[S_EB2 + sel * HH];
        ulonglong2 v0 = bp[0], v1 = bp[1];
        e2p[0] = v0.x; e2p[1] = v0.y; e2p[2] = v1.x; e2p[3] = v1.y;
    }
#pragma unroll
    for (int h = 0; h < HH; h++) {
        const u64 hd = dup2(e1[h]);
        const ulonglong2* wp = (const ulonglong2*)&s[S_EW2 + (sel * HH + h) * HH];
        ulonglong2 w0 = wp[0], w1 = wp[1];
        e2p[0] = ffma2(hd, w0.x, e2p[0]);
        e2p[1] = ffma2(hd, w0.y, e2p[1]);
        e2p[2] = ffma2(hd, w1.x, e2p[2]);
        e2p[3] = ffma2(hd, w1.y, e2p[3]);
    }
    float e2[HH];
    upk2(e2p[0], e2[0], e2[1]); upk2(e2p[1], e2[2], e2[3]);
    upk2(e2p[2], e2[4], e2[5]); upk2(e2p[3], e2[6], e2[7]);
#pragma unroll
    for (int k = 0; k < HH; k++) e2[k] = fmaxf(e2[k], 0.0f);

    {
        const u64* bp = (const u64*)&s[S_EB3 + sel * OO];
        o0 = bp[0]; o1 = bp[1]; o2 = bp[2];
    }
#pragma unroll
    for (int k = 0; k < HH; k++) {
        const u64 kd = dup2(e2[k]);
        const u64* wp = (const u64*)&s[S_EW3 + (sel * HH + k) * OO];
        o0 = ffma2(kd, wp[0], o0);
        o1 = ffma2(kd, wp[1], o1);
        o2 = ffma2(kd, wp[2], o2);
    }
}

__global__ __launch_bounds__(128) void moe_kernel(
    const float* __restrict__ x,
    const float* __restrict__ eW1, const float* __restrict__ eb1,
    const float* __restrict__ eW2, const float* __restrict__ eb2,
    const float* __restrict__ eW3, const float* __restrict__ eb3,
    float* __restrict__ pred, float* __restrict__ glog, int Bhalf)
{
    __shared__ __align__(16) float s[S_TOT];
    const int t = threadIdx.x;
    for (int i = t; i < 544; i += 128) s[S_EW1 + i] = eW1[i];
    if (t < 32)  s[S_EB1 + t] = eb1[t];
    for (int i = t; i < 256; i += 128) s[S_EW2 + i] = eW2[i];
    if (t >= 32 && t < 64) s[S_EB2 + (t - 32)] = eb2[t - 32];
    for (int i = t; i < 192; i += 128) s[S_EW3 + i] = eW3[i];
    if (t >= 64 && t < 88) s[S_EB3 + (t - 64)] = eb3[t - 64];
    __syncthreads();

    const int ba = blockIdx.x * 128 + t;   // first sample
    const int bb = ba + Bhalf;             // second sample (coalesced pairing)

    float xa[DD], xb[DD];
    {
        const float* ra = x + (size_t)ba * DD;
        const float* rb = x + (size_t)bb * DD;
#pragma unroll
        for (int i = 0; i < DD; i++) { xa[i] = ra[i]; xb[i] = rb[i]; }
    }

    // gating layer-2 accumulators (init with bias from constant)
    u64 A2[16], B2[16];
    {
        const ulonglong2* bp = (const ulonglong2*)&cw[C_GB2];
#pragma unroll
        for (int q = 0; q < 8; q++) {
            ulonglong2 v = bp[q];
            A2[2*q] = v.x; A2[2*q+1] = v.y;
            B2[2*q] = v.x; B2[2*q+1] = v.y;
        }
    }

    // layer1 in 16-neuron chunks, fused into layer2; all weight reads warp-uniform const
#pragma unroll
    for (int c = 0; c < 4; c++) {
        u64 A1[8], B1[8];
        {
            const ulonglong2* bp = (const ulonglong2*)&cw[C_GB1 + c * 16];
#pragma unroll
            for (int q = 0; q < 4; q++) {
                ulonglong2 v = bp[q];
                A1[2*q] = v.x; A1[2*q+1] = v.y;
                B1[2*q] = v.x; B1[2*q+1] = v.y;
            }
        }
#pragma unroll
        for (int i = 0; i < DD; i++) {
            const u64 xad = dup2(xa[i]);
            const u64 xbd = dup2(xb[i]);
            const ulonglong2* wp = (const ulonglong2*)&cw[C_GW1 + i * 64 + c * 16];
#pragma unroll
            for (int q = 0; q < 4; q++) {
                ulonglong2 w = wp[q];
                A1[2*q]   = ffma2(xad, w.x, A1[2*q]);
                B1[2*q]   = ffma2(xbd, w.x, B1[2*q]);
                A1[2*q+1] = ffma2(xad, w.y, A1[2*q+1]);
                B1[2*q+1] = ffma2(xbd, w.y, B1[2*q+1]);
            }
        }
#pragma unroll
        for (int p = 0; p < 8; p++) {
            float a0, a1, b0, b1;
            upk2(A1[p], a0, a1);
            upk2(B1[p], b0, b1);
#pragma unroll
            for (int half = 0; half < 2; half++) {
                const u64 had = dup2(fmaxf(half ? a1 : a0, 0.0f));
                const u64 hbd = dup2(fmaxf(half ? b1 : b0, 0.0f));
                const int j = c * 16 + 2 * p + half;
                const ulonglong2* wp = (const ulonglong2*)&cw[C_GW2 + j * 32];
#pragma unroll
                for (int q = 0; q < 8; q++) {
                    ulonglong2 w = wp[q];
                    A2[2*q]   = ffma2(had, w.x, A2[2*q]);
                    B2[2*q]   = ffma2(hbd, w.x, B2[2*q]);
                    A2[2*q+1] = ffma2(had, w.y, A2[2*q+1]);
                    B2[2*q+1] = ffma2(hbd, w.y, B2[2*q+1]);
                }
            }
        }
    }

    // layer 3: relu(h2) -> 4 logits (both samples)
    u64 lgA0, lgA1, lgB0, lgB1;
    {
        ulonglong2 bv = *(const ulonglong2*)&cw[C_GB3];
        lgA0 = bv.x; lgA1 = bv.y;
        lgB0 = bv.x; lgB1 = bv.y;
    }
#pragma unroll
    for (int p = 0; p < 16; p++) {
        float a0, a1, b0, b1;
        upk2(A2[p], a0, a1);
        upk2(B2[p], b0, b1);
#pragma unroll
        for (int half = 0; half < 2; half++) {
            const u64 had = dup2(fmaxf(half ? a1 : a0, 0.0f));
            const u64 hbd = dup2(fmaxf(half ? b1 : b0, 0.0f));
            const int k = 2 * p + half;
            ulonglong2 w = *(const ulonglong2*)&cw[C_GW3 + k * 4];
            lgA0 = ffma2(had, w.x, lgA0);
            lgB0 = ffma2(hbd, w.x, lgB0);
            lgA1 = ffma2(had, w.y, lgA1);
            lgB1 = ffma2(hbd, w.y, lgB1);
        }
    }

    // argmax (first-max-wins) per sample
    float la0, la1, la2, la3, lb0, lb1, lb2, lb3;
    upk2(lgA0, la0, la1); upk2(lgA1, la2, la3);
    upk2(lgB0, lb0, lb1); upk2(lgB1, lb2, lb3);
    int selA = 0; float mA = la0;
    if (la1 > mA) { mA = la1; selA = 1; }
    if (la2 > mA) { mA = la2; selA = 2; }
    if (la3 > mA) { mA = la3; selA = 3; }
    int selB = 0; float mB = lb0;
    if (lb1 > mB) { mB = lb1; selB = 1; }
    if (lb2 > mB) { mB = lb2; selB = 2; }
    if (lb3 > mB) { mB = lb3; selB = 3; }

    u64 oA0, oA1, oA2, oB0, oB1, oB2;
    expert_eval(s, xa, selA, oA0, oA1, oA2);
    expert_eval(s, xb, selB, oB0, oB1, oB2);

    {
        u64* p0 = (u64*)(pred + (size_t)ba * OO);
        p0[0] = oA0; p0[1] = oA1; p0[2] = oA2;
        u64* p1 = (u64*)(pred + (size_t)bb * OO);
        p1[0] = oB0; p1[1] = oB1; p1[2] = oB2;
        ulonglong2* l0 = (ulonglong2*)(glog + (size_t)ba * EE);
        l0[0] = make_ulonglong2(lgA0, lgA1);
        ulonglong2* l1 = (ulonglong2*)(glog + (size_t)bb * EE);
        l1[0] = make_ulonglong2(lgB0, lgB1);
    }
}

extern "C" void kernel_launch(void* const* d_in, const int* in_sizes, int n_in,
                              void* d_out, int out_size) {
    const float* x   = (const float*)d_in[0];
    const float* eW1 = (const float*)d_in[1];
    const float* eb1 = (const float*)d_in[2];
    const float* eW2 = (const float*)d_in[3];
    const float* eb2 = (const float*)d_in[4];
    const float* eW3 = (const float*)d_in[5];
    const float* eb3 = (const float*)d_in[6];
    const float* gW1 = (const float*)d_in[7];
    const float* gb1 = (const float*)d_in[8];
    const float* gW2 = (const float*)d_in[9];
    const float* gb2 = (const float*)d_in[10];
    const float* gW3 = (const float*)d_in[11];
    const float* gb3 = (const float*)d_in[12];

    // stage gating weights into __constant__ (device-to-device async copies;
    // graph-capturable, no allocation)
    cudaMemcpyToSymbolAsync(cw, gW1, 1088 * 4, C_GW1 * 4, cudaMemcpyDeviceToDevice);
    cudaMemcpyToSymbolAsync(cw, gb1,   64 * 4, C_GB1 * 4, cudaMemcpyDeviceToDevice);
    cudaMemcpyToSymbolAsync(cw, gW2, 2048 * 4, C_GW2 * 4, cudaMemcpyDeviceToDevice);
    cudaMemcpyToSymbolAsync(cw, gb2,   32 * 4, C_GB2 * 4, cudaMemcpyDeviceToDevice);
    cudaMemcpyToSymbolAsync(cw, gW3,  128 * 4, C_GW3 * 4, cudaMemcpyDeviceToDevice);
    cudaMemcpyToSymbolAsync(cw, gb3,    4 * 4, C_GB3 * 4, cudaMemcpyDeviceToDevice);

    const int B = in_sizes[0] / DD;
    float* out  = (float*)d_out;
    float* pred = out;                   // [B, 6]
    float* glog = out + (size_t)B * OO;  // [B, 4]

    const int grid = B / 256;            // 128 threads/block, 2 samples/thread
    moe_kernel<<<grid, 128>>>(x, eW1, eb1, eW2, eb2, eW3, eb3,
                              pred, glog, B / 2);
}